// round 16
// baseline (speedup 1.0000x reference)
#include <cuda_runtime.h>
#include <cuda_bf16.h>
#include <cstdint>

#define D_FULL   8192
#define K_NNZ    1024
#define NTHREADS 256
#define SMEM_F2  4096                         // exactly D/2 float2 = 32KB, XOR-swizzled
#define SCALE_F  0.011048543456039806f        // 1/sqrt(8192)

union F2U { float2 f; unsigned long long u; };

// (a,b) -> (a+b, a-b), both components packed. Sub via fma(b,-1,a) (exact).
__device__ __forceinline__ void bfly2(float2& a, float2& b, unsigned long long neg1) {
    F2U x, y, s, d;
    x.f = a; y.f = b;
    asm("add.rn.f32x2 %0, %1, %2;" : "=l"(s.u) : "l"(x.u), "l"(y.u));
    asm("fma.rn.f32x2 %0, %1, %2, %3;" : "=l"(d.u) : "l"(y.u), "l"(neg1), "l"(x.u));
    a = s.f; b = d.f;
}

__device__ __forceinline__ float2 pmul2(float2 a, unsigned long long sc) {
    F2U x, r; x.f = a;
    asm("mul.rn.f32x2 %0, %1, %2;" : "=l"(r.u) : "l"(x.u), "l"(sc));
    return r.f;
}

// radix-16 butterfly network over the 4 in-thread j-bits (packed over float2)
__device__ __forceinline__ void radix16(float2 v[16], unsigned long long neg1) {
#pragma unroll
    for (int h = 1; h < 16; h <<= 1) {
#pragma unroll
        for (int i = 0; i < 16; i++) {
            if ((i & h) == 0) bfly2(v[i], v[i + h], neg1);
        }
    }
}

// Single swizzled layout for the whole kernel:
//   phys(j) = j ^ (((j >> 5) & 15) << 1)      (bijective on [0,4096))
// Conflict-free for all passes (verified per pass: bank bits get XORed with a
// lane-distinct value), and every pass stores to the SAME slots it loaded
// (in-place, one owner per slot per pass -> no intra-pass barrier needed).
__device__ __forceinline__ int SWZ(int j) { return j ^ (((j >> 5) & 15) << 1); }

__global__ void __launch_bounds__(NTHREADS, 6)
fwht_kernel(const float* __restrict__ u,
            const int*   __restrict__ idx,
            float*       __restrict__ out)
{
    __shared__ __align__(16) float2 Z[SMEM_F2];
    float*  zf = reinterpret_cast<float*>(Z);
    float4* z4 = reinterpret_cast<float4*>(Z);

    const int t   = threadIdx.x;
    const int l   = t & 31;
    const int w   = t >> 5;
    const int row = blockIdx.x;

    F2U negu; negu.f = make_float2(-1.0f, -1.0f);
    F2U scu;  scu.f  = make_float2(SCALE_F, SCALE_F);
    const unsigned long long NEG1 = negu.u;
    const unsigned long long SC2  = scu.u;

    // ---- zero all 4096 float2 = 2048 float4, 8 per thread ----
#pragma unroll
    for (int i = 0; i < 8; i++)
        z4[t + 256 * i] = make_float4(0.f, 0.f, 0.f, 0.f);
    __syncthreads();

    // ---- scatter. float elem e -> float2 j=e>>1, comp e&1; swizzled addr.
    //      idx sorted; plain store unless a sorted neighbor matches. ----
    {
        const int4   id = reinterpret_cast<const int4*>(idx)[t];
        const float4 uu = reinterpret_cast<const float4*>(u + (size_t)row * K_NNZ)[t];
        const int prev = (t > 0)            ? idx[4 * t - 1] : -1;
        const int nxt  = (t < NTHREADS - 1) ? idx[4 * t + 4] : -1;

        const int ax = 2 * SWZ(id.x >> 1) + (id.x & 1);
        const int ay = 2 * SWZ(id.y >> 1) + (id.y & 1);
        const int az = 2 * SWZ(id.z >> 1) + (id.z & 1);
        const int aw = 2 * SWZ(id.w >> 1) + (id.w & 1);

        if (id.x != prev && id.x != id.y) zf[ax] = uu.x; else atomicAdd(&zf[ax], uu.x);
        if (id.y != id.x && id.y != id.z) zf[ay] = uu.y; else atomicAdd(&zf[ay], uu.y);
        if (id.z != id.y && id.z != id.w) zf[az] = uu.z; else atomicAdd(&zf[az], uu.z);
        if (id.w != id.z && id.w != nxt)  zf[aw] = uu.w; else atomicAdd(&zf[aw], uu.w);
    }
    __syncthreads();

    float2 v[16];

    // ---- Pass A: j = l + 32T + 512w (T = j-bits 8..5 = elem bits 9..6).
    //      (j>>5)&15 = T, so phys = (l + 32T + 512w) ^ (2T). In-place. ----
    {
        const int base = l + 512 * w;
#pragma unroll
        for (int T = 0; T < 16; T++) v[T] = Z[(base + 32 * T) ^ (2 * T)];

        radix16(v, NEG1);

#pragma unroll
        for (int T = 0; T < 16; T++) Z[(base + 32 * T) ^ (2 * T)] = v[T];
    }
    __syncthreads();

    // ---- Pass B: j = (w&1) + 2T + 32l + 1024(w>>1) (T = j-bits 4..1 = elem bits 5..2).
    //      (j>>5)&15 = l&15, so phys = C + 2*(T ^ (l&15)). In-place. ----
    {
        const int m  = l & 15;
        const int C  = (w & 1) + 32 * l + 1024 * (w >> 1);
#pragma unroll
        for (int T = 0; T < 16; T++) v[T] = Z[C + 2 * (T ^ m)];

        radix16(v, NEG1);

#pragma unroll
        for (int T = 0; T < 16; T++) Z[C + 2 * (T ^ m)] = v[T];
    }
    __syncthreads();

    // ---- Pass C: j = (T&1) + 2l + 64w + 512(T>>1)
    //      (T&1 = elem bit 1, T>>1 = elem bits 12..10; then intra bit + scale).
    //      (j>>5)&15 = (l>>4) + 2w -> constant XOR folds into the base. ----
    {
        const int m2 = (l >> 4) + 2 * w;
        const int C2 = 2 * ((l & 15) ^ m2) + 32 * (l >> 4) + 64 * w;
#pragma unroll
        for (int T = 0; T < 16; T++)
            v[T] = Z[C2 + (T & 1) + 512 * (T >> 1)];

        radix16(v, NEG1);

        // scale (commutes with the final butterfly), packed
#pragma unroll
        for (int T = 0; T < 16; T++) v[T] = pmul2(v[T], SC2);

        // out elem e = c + 2(T&1) + 4l + 128w + 1024(T>>1); float4 idx = l + 32w + 256s
        float4* o4 = reinterpret_cast<float4*>(out) + ((size_t)row * (D_FULL / 4) + l + 32 * w);
#pragma unroll
        for (int s = 0; s < 8; s++) {
            float2 a = v[2 * s];
            float2 b = v[2 * s + 1];
            float4 st;
            st.x = a.x + a.y;   // e%4==0 (j even, c=0)
            st.y = a.x - a.y;   // e%4==1 (j even, c=1)
            st.z = b.x + b.y;   // e%4==2 (j odd,  c=0)
            st.w = b.x - b.y;   // e%4==3 (j odd,  c=1)
            o4[256 * s] = st;
        }
    }
}

extern "C" void kernel_launch(void* const* d_in, const int* in_sizes, int n_in,
                              void* d_out, int out_size)
{
    const float* u   = (const float*)d_in[0];   // (4, 2048, 1024) fp32
    const int*   idx = (const int*)d_in[1];     // (1024,) int32, sorted
    float*       out = (float*)d_out;           // (4, 2048, 8192) fp32

    const int rows = in_sizes[0] / K_NNZ;       // 8192
    fwht_kernel<<<rows, NTHREADS>>>(u, idx, out);
}

// round 17
// speedup vs baseline: 1.3794x; 1.3794x over previous
#include <cuda_runtime.h>
#include <cuda_bf16.h>
#include <cstdint>

#define D_FULL   8192
#define K_NNZ    1024
#define NTHREADS 256
#define SMEM_F2  4478                         // max of psi2 image + 1
#define SCALE_F  0.011048543456039806f        // 1/sqrt(8192)

union F2U { float2 f; unsigned long long u; };

// (a,b) -> (a+b, a-b), both components packed. Sub via fma(b,-1,a) (exact).
__device__ __forceinline__ void bfly2(float2& a, float2& b, unsigned long long neg1) {
    F2U x, y, s, d;
    x.f = a; y.f = b;
    asm("add.rn.f32x2 %0, %1, %2;" : "=l"(s.u) : "l"(x.u), "l"(y.u));
    asm("fma.rn.f32x2 %0, %1, %2, %3;" : "=l"(d.u) : "l"(y.u), "l"(neg1), "l"(x.u));
    a = s.f; b = d.f;
}

__device__ __forceinline__ float2 pmul2(float2 a, unsigned long long sc) {
    F2U x, r; x.f = a;
    asm("mul.rn.f32x2 %0, %1, %2;" : "=l"(r.u) : "l"(x.u), "l"(sc));
    return r.f;
}

// radix-16 butterfly network over the 4 in-thread j-bits (packed over float2)
__device__ __forceinline__ void radix16(float2 v[16], unsigned long long neg1) {
#pragma unroll
    for (int h = 1; h < 16; h <<= 1) {
#pragma unroll
        for (int i = 0; i < 16; i++) {
            if ((i & h) == 0) bfly2(v[i], v[i + h], neg1);
        }
    }
}

__global__ void __launch_bounds__(NTHREADS, 6)
fwht_kernel(const float* __restrict__ u,
            const int*   __restrict__ idx,
            float*       __restrict__ out)
{
    // float2 element j holds output/input elems (2j, 2j+1). j in [0,4096).
    // Stage layouts (bijective PADDINGS — conflict-free for float2 (8B) access,
    // verified by measurement in R14; the XOR-swizzle variant was NOT):
    //   psi0(j) = j                      scatter -> A   (A load: lane-contiguous)
    //   psi1(j) = j + (j>>5)             A -> B         (store stride1, load stride33)
    //   psi2(j) = j + (j>>4) + (j>>5)    B -> C         (store stride35, load stride2+(l>>3))
    // Passes transform IN PLACE between different layouts, so each pass has a
    // barrier between its register-load phase and its store phase (values sit
    // in registers across the barrier).
    __shared__ __align__(16) float2 Z[SMEM_F2];
    float*  zf = reinterpret_cast<float*>(Z);
    float4* z4 = reinterpret_cast<float4*>(Z);

    const int t   = threadIdx.x;
    const int l   = t & 31;
    const int w   = t >> 5;
    const int row = blockIdx.x;

    F2U negu; negu.f = make_float2(-1.0f, -1.0f);
    F2U scu;  scu.f  = make_float2(SCALE_F, SCALE_F);
    const unsigned long long NEG1 = negu.u;
    const unsigned long long SC2  = scu.u;

    // ---- zero the psi0 region: 4096 float2 = 2048 float4, 8 per thread ----
#pragma unroll
    for (int i = 0; i < 8; i++)
        z4[t + 256 * i] = make_float4(0.f, 0.f, 0.f, 0.f);
    __syncthreads();

    // ---- scatter (identity layout: float index == elem index). idx sorted;
    //      plain store unless a sorted neighbor matches (then atomic). ----
    {
        const int4   id = reinterpret_cast<const int4*>(idx)[t];
        const float4 uu = reinterpret_cast<const float4*>(u + (size_t)row * K_NNZ)[t];
        const int prev = (t > 0)            ? idx[4 * t - 1] : -1;
        const int nxt  = (t < NTHREADS - 1) ? idx[4 * t + 4] : -1;

        if (id.x != prev && id.x != id.y) zf[id.x] = uu.x; else atomicAdd(&zf[id.x], uu.x);
        if (id.y != id.x && id.y != id.z) zf[id.y] = uu.y; else atomicAdd(&zf[id.y], uu.y);
        if (id.z != id.y && id.z != id.w) zf[id.z] = uu.z; else atomicAdd(&zf[id.z], uu.z);
        if (id.w != id.z && id.w != nxt)  zf[id.w] = uu.w; else atomicAdd(&zf[id.w], uu.w);
    }
    __syncthreads();

    float2 v[16];

    // ---- Pass A: j = l + 32T + 512w. Butterflies j-bits {8..5} (=T). ----
    {
        const float2* src = Z + (l + 512 * w);            // psi0: lane-contiguous
#pragma unroll
        for (int T = 0; T < 16; T++) v[T] = src[32 * T];

        radix16(v, NEG1);

        __syncthreads();   // all psi0 reads done before any psi1 write

        float2* dst = Z + (l + 528 * w);                  // psi1: phys = l + 33T + 528w
#pragma unroll
        for (int T = 0; T < 16; T++) dst[33 * T] = v[T];
    }
    __syncthreads();

    // ---- Pass B: j = (w&1) + 2T + 32l + 1024(w>>1). Butterflies j-bits {4..1} (=T). ----
    {
        const float2* src = Z + ((w & 1) + 33 * l + 1056 * (w >> 1));   // psi1
#pragma unroll
        for (int T = 0; T < 16; T++) v[T] = src[2 * T];

        radix16(v, NEG1);

        __syncthreads();   // all psi1 reads done before any psi2 write

        float2* dst = Z + ((w & 1) + 35 * l + 1120 * (w >> 1));         // psi2
#pragma unroll
        for (int T = 0; T < 16; T++) dst[2 * T + (T >> 3)] = v[T];
    }
    __syncthreads();

    // ---- Pass C: j = (T&1) + 2l + 64w + 512(T>>1).
    //      Butterflies j-bits {0} (h=1) and {9,10,11} (h=2,4,8) = radix16 over T,
    //      then the intra-float2 stage (elem bit 0) + scale, then coalesced STG. ----
    {
        const float2* src = Z + (2 * l + (l >> 3) + (l >> 4) + 70 * w); // psi2
#pragma unroll
        for (int T = 0; T < 16; T++) v[T] = src[(T & 1) + 560 * (T >> 1)];

        radix16(v, NEG1);

        // scale first (commutes with the last butterfly), packed
#pragma unroll
        for (int T = 0; T < 16; T++) v[T] = pmul2(v[T], SC2);

        // out elem e = c + 2j = c + 2(T&1) + 4l + 128w + 1024(T>>1)
        // float4 index = l + 32w + 256s for s = T>>1; lanes contiguous -> coalesced
        float4* o4 = reinterpret_cast<float4*>(out) + ((size_t)row * (D_FULL / 4) + l + 32 * w);
#pragma unroll
        for (int s = 0; s < 8; s++) {
            float2 a = v[2 * s];
            float2 b = v[2 * s + 1];
            float4 st;
            st.x = a.x + a.y;   // e%4==0 : c-stage sum  (j even)
            st.y = a.x - a.y;   // e%4==1 : c-stage diff (j even)
            st.z = b.x + b.y;   // e%4==2 : j odd
            st.w = b.x - b.y;   // e%4==3
            o4[256 * s] = st;
        }
    }
}

extern "C" void kernel_launch(void* const* d_in, const int* in_sizes, int n_in,
                              void* d_out, int out_size)
{
    const float* u   = (const float*)d_in[0];   // (4, 2048, 1024) fp32
    const int*   idx = (const int*)d_in[1];     // (1024,) int32, sorted
    float*       out = (float*)d_out;           // (4, 2048, 8192) fp32

    const int rows = in_sizes[0] / K_NNZ;       // 8192
    fwht_kernel<<<rows, NTHREADS>>>(u, idx, out);
}